// round 7
// baseline (speedup 1.0000x reference)
#include <cuda_runtime.h>

#define N_NODES 100000
#define N_EDGES 1000000
#define N_GRAPHS 2048
#define SCAN_BS 512
#define SCAN_NB ((N_NODES + SCAN_BS - 1) / SCAN_BS)

typedef unsigned long long u64;

// ---------------- device scratch (no allocs allowed) ----------------
__device__ float g_hA[N_NODES * 64];
__device__ float g_hB[N_NODES * 64];
__device__ float g_mean[N_NODES * 64];
__device__ float g_Ep[128 * 64];          // emb @ W1l  (32 KB, L1-resident)
__device__ float g_Rp[128 * 64];          // emb @ W1r
__device__ int   g_deg[N_NODES];          // INVARIANT: zero at kernel_launch entry
__device__ int   g_rowptr[N_NODES + 1];
__device__ int   g_cursor[N_NODES];
__device__ int   g_colsrc[N_EDGES];       // packed: src_node | (vocab_id << 20)
__device__ u64   g_lb[SCAN_NB];

// ---------------- f32x2 packed helpers ----------------
__device__ __forceinline__ u64 pk2(float x) {
    u64 r; asm("mov.b64 %0, {%1, %1};" : "=l"(r) : "f"(x)); return r;
}
__device__ __forceinline__ void fma2(u64 &d, u64 a, u64 b) {
    asm("fma.rn.f32x2 %0, %1, %2, %0;" : "+l"(d) : "l"(a), "l"(b));
}
__device__ __forceinline__ void add2(u64 &d, u64 a) {
    asm("add.rn.f32x2 %0, %0, %1;" : "+l"(d) : "l"(a));
}
__device__ __forceinline__ float2 up2(u64 v) {
    float lo, hi; asm("mov.b64 {%0, %1}, %2;" : "=f"(lo), "=f"(hi) : "l"(v));
    float2 f; f.x = lo; f.y = hi; return f;
}

// ---------- launch 1: E'=emb@W1l, R'=emb@W1r  +  dst histogram + lb reset ----
__global__ void k_prep(const float* __restrict__ emb, const float* __restrict__ W1l,
                       const float* __restrict__ W1r, const int* __restrict__ dst) {
    int b = blockIdx.x, t = threadIdx.x;
    if (b < 128) {
        __shared__ float se[64];
        if (b == 0) for (int i = t; i < SCAN_NB; i += 128) g_lb[i] = 0ULL;
        if (t < 64) se[t] = emb[b * 64 + t];
        __syncthreads();
        const float* W = (t < 64) ? W1l : W1r;
        int c = t & 63;
        float acc = 0.f;
#pragma unroll 8
        for (int k = 0; k < 64; k++) acc += se[k] * __ldg(W + k * 64 + c);
        if (t < 64) g_Ep[b * 64 + c] = acc; else g_Rp[b * 64 + c] = acc;
    } else {
        int base = (b - 128) * 512;                 // 512 edges per block
        int e0 = base + 2 * t;
        if (e0 < N_EDGES) atomicAdd(&g_deg[__ldg(dst + e0)], 1);
        if (e0 + 1 < N_EDGES) atomicAdd(&g_deg[__ldg(dst + e0 + 1)], 1);
    }
}

// ---------------- launch 2: single-pass decoupled-lookback scan -------------
__global__ void __launch_bounds__(SCAN_BS) k_scanlb() {
    __shared__ int s[SCAN_BS];
    __shared__ int s_prefix;
    int t = threadIdx.x, bid = blockIdx.x;
    int i = bid * SCAN_BS + t;
    int v = (i < N_NODES) ? g_deg[i] : 0;
    s[t] = v;
    __syncthreads();
    for (int off = 1; off < SCAN_BS; off <<= 1) {
        int x = (t >= off) ? s[t - off] : 0;
        __syncthreads();
        s[t] += x;
        __syncthreads();
    }
    int incl = s[t];
    int total = s[SCAN_BS - 1];
    if (t < 32) {
        unsigned prefix = 0;
        if (bid == 0) {
            if (t == 0) atomicExch(&g_lb[0], (2ULL << 32) | (unsigned)total);
        } else {
            if (t == 0) atomicExch(&g_lb[bid], (1ULL << 32) | (unsigned)total);
            int p = bid - 1;
            while (true) {
                int idx = p - t;
                u64 st = 0;
                if (idx >= 0) {
                    do { st = atomicAdd(&g_lb[idx], 0ULL); } while ((st >> 32) == 0);
                }
                unsigned pm = __ballot_sync(0xffffffffu, idx >= 0 && (st >> 32) == 2);
                unsigned val;
                if (pm) {
                    int closest = __ffs(pm) - 1;
                    val = (t <= closest) ? (unsigned)st : 0u;
                } else {
                    val = (idx >= 0) ? (unsigned)st : 0u;
                }
#pragma unroll
                for (int o = 16; o; o >>= 1) val += __shfl_xor_sync(0xffffffffu, val, o);
                prefix += val;
                if (pm) break;
                p -= 32;
            }
            if (t == 0) atomicExch(&g_lb[bid], (2ULL << 32) | (unsigned)(prefix + (unsigned)total));
        }
        if (t == 0) s_prefix = (int)prefix;
    }
    __syncthreads();
    int excl = incl - v + s_prefix;
    if (i < N_NODES) {
        g_rowptr[i] = excl;
        g_cursor[i] = excl;
        if (i == N_NODES - 1) g_rowptr[N_NODES] = excl + v;
    }
}

// ------- launch 3: CSR fill (packed node|vid) + restore deg invariant -------
__global__ void k_fill(const int* __restrict__ src, const int* __restrict__ dst,
                       const int* __restrict__ x) {
    int e = blockIdx.x * blockDim.x + threadIdx.x;
    if (e < N_NODES) g_deg[e] = 0;
    if (e >= N_EDGES) return;
    int sn = __ldg(src + e);
    int packed = sn | (__ldg(x + sn) << 20);
    int p = atomicAdd(&g_cursor[dst[e]], 1);
    g_colsrc[p] = packed;
}

// ---------------- aggregation core (f32x2 accumulate, 8 edges/iter) ---------
// half-warp per edge pair stream; each lane owns a float4 (= 2 f32x2) group.
template <bool UseVid>
__device__ __forceinline__ void agg_core(const float* __restrict__ base,
                                         int s, int e, int half, int fb,
                                         u64 &A, u64 &B) {
    u64 a0 = 0, b0 = 0, a1 = 0, b1 = 0;
    int i = s;
    for (; i + 8 <= e; i += 8) {
        int u0 = __ldg(g_colsrc + i + half);
        int u1 = __ldg(g_colsrc + i + 2 + half);
        int u2 = __ldg(g_colsrc + i + 4 + half);
        int u3 = __ldg(g_colsrc + i + 6 + half);
        int r0 = UseVid ? (u0 >> 20) : (u0 & 0xFFFFF);
        int r1 = UseVid ? (u1 >> 20) : (u1 & 0xFFFFF);
        int r2 = UseVid ? (u2 >> 20) : (u2 & 0xFFFFF);
        int r3 = UseVid ? (u3 >> 20) : (u3 & 0xFFFFF);
        ulonglong2 v0 = *(const ulonglong2*)(base + r0 * 64 + fb);
        ulonglong2 v1 = *(const ulonglong2*)(base + r1 * 64 + fb);
        ulonglong2 v2 = *(const ulonglong2*)(base + r2 * 64 + fb);
        ulonglong2 v3 = *(const ulonglong2*)(base + r3 * 64 + fb);
        add2(a0, v0.x); add2(b0, v0.y);
        add2(a1, v1.x); add2(b1, v1.y);
        add2(a0, v2.x); add2(b0, v2.y);
        add2(a1, v3.x); add2(b1, v3.y);
    }
    for (; i + 2 <= e; i += 2) {
        int u = __ldg(g_colsrc + i + half);
        int r = UseVid ? (u >> 20) : (u & 0xFFFFF);
        ulonglong2 v = *(const ulonglong2*)(base + r * 64 + fb);
        add2(a0, v.x); add2(b0, v.y);
    }
    if (i < e && half == 0) {
        int u = __ldg(g_colsrc + i);
        int r = UseVid ? (u >> 20) : (u & 0xFFFFF);
        ulonglong2 v = *(const ulonglong2*)(base + r * 64 + fb);
        add2(a0, v.x); add2(b0, v.y);
    }
    add2(a0, a1); add2(b0, b1);
    // cross-half reduce (u64 shfl = 2x SHFL.b32)
    u64 sa = __shfl_xor_sync(0xffffffffu, a0, 16);
    u64 sb = __shfl_xor_sync(0xffffffffu, b0, 16);
    add2(a0, sa); add2(b0, sb);
    A = a0; B = b0;
}

// launch 4 [capture slot]: conv1 fully fused — relu(mean(E'[vid]) + R'[x_n] + b1)
__global__ void k_agg1(const int* __restrict__ x, const float* __restrict__ b1,
                       float* __restrict__ out) {
    int w = (blockIdx.x * blockDim.x + threadIdx.x) >> 5;
    if (w >= N_NODES) return;
    int lane = threadIdx.x & 31;
    int half = lane >> 4;
    int fb = (lane & 15) * 4;
    int s = g_rowptr[w], e = g_rowptr[w + 1];
    u64 A, B;
    agg_core<true>(g_Ep, s, e, half, fb, A, B);
    if (half == 0) {
        float inv = __fdividef(1.f, (float)max(e - s, 1));
        float2 p = up2(A), q = up2(B);
        int vid = __ldg(x + w);
        float4 r = *(const float4*)(g_Rp + vid * 64 + fb);
        float4 bb = *(const float4*)(b1 + fb);
        float4 o;
        o.x = fmaxf(fmaf(p.x, inv, r.x + bb.x), 0.f);
        o.y = fmaxf(fmaf(p.y, inv, r.y + bb.y), 0.f);
        o.z = fmaxf(fmaf(q.x, inv, r.z + bb.z), 0.f);
        o.w = fmaxf(fmaf(q.y, inv, r.w + bb.w), 0.f);
        *(float4*)(out + w * 64 + fb) = o;
    }
}

// launch 5: conv2 aggregation (plain mean over node rows)
__global__ void k_agg(const float* __restrict__ h, float* __restrict__ mean) {
    int w = (blockIdx.x * blockDim.x + threadIdx.x) >> 5;
    if (w >= N_NODES) return;
    int lane = threadIdx.x & 31;
    int half = lane >> 4;
    int fb = (lane & 15) * 4;
    int s = g_rowptr[w], e = g_rowptr[w + 1];
    u64 A, B;
    agg_core<false>(h, s, e, half, fb, A, B);
    if (half == 0) {
        float inv = __fdividef(1.f, (float)max(e - s, 1));
        float2 p = up2(A), q = up2(B);
        float4 o; o.x = p.x * inv; o.y = p.y * inv; o.z = q.x * inv; o.w = q.y * inv;
        *(float4*)(mean + w * 64 + fb) = o;
    }
}

// ---------------- launch 6: conv2 dual GEMM + bias + relu -------------------
__global__ void __launch_bounds__(256)
k_mm(const float* __restrict__ Am, const float* __restrict__ Ah,
     const float* __restrict__ Wl, const float* __restrict__ Wr,
     const float* __restrict__ bias, float* __restrict__ out) {
    __shared__ ulonglong2 sWl[64 * 16];
    __shared__ ulonglong2 sWr[64 * 16];
    __shared__ u64 sB[32];
    int t = threadIdx.x;
    const ulonglong2* gWl = (const ulonglong2*)Wl;
    const ulonglong2* gWr = (const ulonglong2*)Wr;
    for (int i = t; i < 1024; i += 256) { sWl[i] = gWl[i]; sWr[i] = gWr[i]; }
    if (t < 32) sB[t] = ((const u64*)bias)[t];
    __syncthreads();
    int n = blockIdx.x * 256 + t;
    if (n >= N_NODES) return;

    u64 acc[32];
#pragma unroll
    for (int j = 0; j < 32; j++) acc[j] = sB[j];

    const float4* am4 = (const float4*)(Am + n * 64);
    const float4* ah4 = (const float4*)(Ah + n * 64);
#pragma unroll 4
    for (int k0 = 0; k0 < 16; k0++) {
        float4 a4 = __ldg(am4 + k0);
        float4 c4 = __ldg(ah4 + k0);
        float av[4] = {a4.x, a4.y, a4.z, a4.w};
        float cv[4] = {c4.x, c4.y, c4.z, c4.w};
#pragma unroll
        for (int kk = 0; kk < 4; kk++) {
            u64 a2 = pk2(av[kk]);
            u64 c2 = pk2(cv[kk]);
            const ulonglong2* wl = sWl + (k0 * 4 + kk) * 16;
            const ulonglong2* wr = sWr + (k0 * 4 + kk) * 16;
#pragma unroll
            for (int j = 0; j < 16; j++) {
                ulonglong2 l = wl[j], r = wr[j];
                fma2(acc[2 * j],     a2, l.x);
                fma2(acc[2 * j + 1], a2, l.y);
                fma2(acc[2 * j],     c2, r.x);
                fma2(acc[2 * j + 1], c2, r.y);
            }
        }
    }

    float4* o4 = (float4*)(out + n * 64);
#pragma unroll
    for (int j = 0; j < 16; j++) {
        float2 p = up2(acc[2 * j]);
        float2 q = up2(acc[2 * j + 1]);
        float4 o;
        o.x = fmaxf(p.x, 0.f); o.y = fmaxf(p.y, 0.f);
        o.z = fmaxf(q.x, 0.f); o.w = fmaxf(q.y, 0.f);
        o4[j] = o;
    }
}

// ---------------- launch 7: mean-pool + output head (warp per graph) --------
__global__ void k_pool(const float* __restrict__ h, const int* __restrict__ batch,
                       const float* __restrict__ Wout, const float* __restrict__ bout,
                       float* __restrict__ out) {
    int g = (blockIdx.x * blockDim.x + threadIdx.x) >> 5;
    if (g >= N_GRAPHS) return;
    int lane = threadIdx.x & 31;
    int s, e;
    { int lo = 0, hi = N_NODES;
      while (lo < hi) { int m = (lo + hi) >> 1; if (__ldg(batch + m) < g) lo = m + 1; else hi = m; }
      s = lo; }
    { int lo = s, hi = N_NODES;
      while (lo < hi) { int m = (lo + hi) >> 1; if (__ldg(batch + m) < g + 1) lo = m + 1; else hi = m; }
      e = lo; }
    float a0 = 0.f, a1 = 0.f;
#pragma unroll 4
    for (int n = s; n < e; ++n) {
        a0 += h[n * 64 + lane];
        a1 += h[n * 64 + lane + 32];
    }
    float inv = __fdividef(1.f, (float)max(e - s, 1));
    a0 *= inv; a1 *= inv;
    float p0 = a0 * __ldg(Wout + lane * 2 + 0) + a1 * __ldg(Wout + (lane + 32) * 2 + 0);
    float p1 = a0 * __ldg(Wout + lane * 2 + 1) + a1 * __ldg(Wout + (lane + 32) * 2 + 1);
#pragma unroll
    for (int off = 16; off; off >>= 1) {
        p0 += __shfl_xor_sync(0xffffffffu, p0, off);
        p1 += __shfl_xor_sync(0xffffffffu, p1, off);
    }
    if (lane == 0) {
        out[g * 2 + 0] = p0 + __ldg(bout + 0);
        out[g * 2 + 1] = p1 + __ldg(bout + 1);
    }
}

// ---------------- launch ----------------
extern "C" void kernel_launch(void* const* d_in, const int* in_sizes, int n_in,
                              void* d_out, int out_size) {
    const int*   x     = (const int*)d_in[0];
    const int*   ei    = (const int*)d_in[1];
    const int*   batch = (const int*)d_in[2];
    const float* emb   = (const float*)d_in[3];
    const float* W1l   = (const float*)d_in[4];
    const float* b1    = (const float*)d_in[5];
    const float* W1r   = (const float*)d_in[6];
    const float* W2l   = (const float*)d_in[7];
    const float* b2    = (const float*)d_in[8];
    const float* W2r   = (const float*)d_in[9];
    const float* Wo    = (const float*)d_in[10];
    const float* bo    = (const float*)d_in[11];
    const int* src = ei;
    const int* dst = ei + N_EDGES;
    float* out = (float*)d_out;

    float *hA, *hB, *mean;
    cudaGetSymbolAddress((void**)&hA, g_hA);
    cudaGetSymbolAddress((void**)&hB, g_hB);
    cudaGetSymbolAddress((void**)&mean, g_mean);

    // 1: weight transform + dst histogram + lb reset
    k_prep<<<128 + ((N_EDGES + 511) / 512), 256>>>(emb, W1l, W1r, dst);
    // 2: rowptr/cursor via lookback scan
    k_scanlb<<<SCAN_NB, SCAN_BS>>>();
    // 3: CSR fill, packed node|vid (+ restore deg==0)
    k_fill<<<(N_EDGES + 255) / 256, 256>>>(src, dst, x);

    // 4: conv1 fully fused (L1-resident E' gather)   <-- ncu capture slot
    k_agg1<<<(N_NODES * 32 + 255) / 256, 256>>>(x, b1, hB);

    // 5-6: conv2
    k_agg<<<(N_NODES * 32 + 255) / 256, 256>>>(hB, mean);
    k_mm<<<(N_NODES + 255) / 256, 256>>>(mean, hB, W2l, W2r, b2, hA);

    // 7: pool + head
    k_pool<<<(N_GRAPHS * 32 + 255) / 256, 256>>>(hA, batch, Wo, bo, out);
}